// round 1
// baseline (speedup 1.0000x reference)
#include <cuda_runtime.h>
#include <cuda_bf16.h>
#include <math.h>

// Problem dims
#define Bz   4
#define Sq   4096
#define Dd   1024          // D_IN == D_OUT
#define MS   (Bz * Sq)     // 16384 rows for projections

// ---------------- scratch (device globals; no allocations allowed) --------
__device__ float g_Q[(size_t)Bz * Sq * Dd];
__device__ float g_K[(size_t)Bz * Sq * Dd];
__device__ float g_V[(size_t)Bz * Sq * Dd];
__device__ float g_S[(size_t)Bz * Sq * Sq];   // scores / probs, 268 MB

// ===========================================================================
// Kernel 1: fused QKV projection.  C[m,n] = sum_k X[m,k] * W[n,k]
// 128x128x8 tile, 256 threads, 8x8 micro-tile. Both A and B are K-major.
// grid = (DOUT/128, MS/128, 3)
// ===========================================================================
__global__ __launch_bounds__(256, 2)
void qkv_gemm(const float* __restrict__ X,
              const float* __restrict__ Wq,
              const float* __restrict__ Wk,
              const float* __restrict__ Wv)
{
    const float* W = (blockIdx.z == 0) ? Wq : (blockIdx.z == 1) ? Wk : Wv;
    float*       O = (blockIdx.z == 0) ? g_Q : (blockIdx.z == 1) ? g_K : g_V;

    const int m0 = blockIdx.y * 128;
    const int n0 = blockIdx.x * 128;
    const int tid = threadIdx.x;

    __shared__ float As[8][128];
    __shared__ float Bs[8][128];

    const int lrow = tid >> 1;
    const int lk   = (tid & 1) * 4;
    const float* Aptr = X + (size_t)(m0 + lrow) * Dd + lk;
    const float* Bptr = W + (size_t)(n0 + lrow) * Dd + lk;

    const int ty = tid >> 4;   // 0..15
    const int tx = tid & 15;   // 0..15

    float acc[8][8];
#pragma unroll
    for (int i = 0; i < 8; i++)
#pragma unroll
        for (int j = 0; j < 8; j++) acc[i][j] = 0.f;

    for (int k0 = 0; k0 < Dd; k0 += 8) {
        float4 a4 = *(const float4*)(Aptr + k0);
        float4 b4 = *(const float4*)(Bptr + k0);
        __syncthreads();
        As[lk + 0][lrow] = a4.x; As[lk + 1][lrow] = a4.y;
        As[lk + 2][lrow] = a4.z; As[lk + 3][lrow] = a4.w;
        Bs[lk + 0][lrow] = b4.x; Bs[lk + 1][lrow] = b4.y;
        Bs[lk + 2][lrow] = b4.z; Bs[lk + 3][lrow] = b4.w;
        __syncthreads();
#pragma unroll
        for (int kk = 0; kk < 8; kk++) {
            float ar[8], br[8];
            *(float4*)&ar[0] = *(const float4*)&As[kk][ty * 4];
            *(float4*)&ar[4] = *(const float4*)&As[kk][64 + ty * 4];
            *(float4*)&br[0] = *(const float4*)&Bs[kk][tx * 4];
            *(float4*)&br[4] = *(const float4*)&Bs[kk][64 + tx * 4];
#pragma unroll
            for (int i = 0; i < 8; i++)
#pragma unroll
                for (int j = 0; j < 8; j++)
                    acc[i][j] += ar[i] * br[j];
        }
    }

#pragma unroll
    for (int mi = 0; mi < 2; mi++)
#pragma unroll
        for (int i = 0; i < 4; i++) {
            int row = m0 + mi * 64 + ty * 4 + i;
#pragma unroll
            for (int ni = 0; ni < 2; ni++) {
                int col = n0 + ni * 64 + tx * 4;
                float4 v = make_float4(acc[mi * 4 + i][ni * 4 + 0],
                                       acc[mi * 4 + i][ni * 4 + 1],
                                       acc[mi * 4 + i][ni * 4 + 2],
                                       acc[mi * 4 + i][ni * 4 + 3]);
                *(float4*)(O + (size_t)row * Dd + col) = v;
            }
        }
}

// ===========================================================================
// Kernel 2: block-causal scores.  S[b,q,k] = scale * dot(Q[b,q,:], K[b,k,:])
// grid = (S/128 kt, S/128 qt, B); tiles with kt > qt exit immediately.
// ===========================================================================
__global__ __launch_bounds__(256, 2)
void scores_gemm()
{
    const int kt = blockIdx.x, qt = blockIdx.y, b = blockIdx.z;
    if (kt > qt) return;

    const float scale = 0.03125f;  // 1/sqrt(1024)
    const float* Qb = g_Q + (size_t)b * Sq * Dd;
    const float* Kb = g_K + (size_t)b * Sq * Dd;
    float*       Sb = g_S + (size_t)b * Sq * Sq;

    const int m0 = qt * 128;
    const int n0 = kt * 128;
    const int tid = threadIdx.x;

    __shared__ float As[8][128];
    __shared__ float Bs[8][128];

    const int lrow = tid >> 1;
    const int lk   = (tid & 1) * 4;
    const float* Aptr = Qb + (size_t)(m0 + lrow) * Dd + lk;
    const float* Bptr = Kb + (size_t)(n0 + lrow) * Dd + lk;

    const int ty = tid >> 4, tx = tid & 15;

    float acc[8][8];
#pragma unroll
    for (int i = 0; i < 8; i++)
#pragma unroll
        for (int j = 0; j < 8; j++) acc[i][j] = 0.f;

    for (int k0 = 0; k0 < Dd; k0 += 8) {
        float4 a4 = *(const float4*)(Aptr + k0);
        float4 b4 = *(const float4*)(Bptr + k0);
        __syncthreads();
        As[lk + 0][lrow] = a4.x; As[lk + 1][lrow] = a4.y;
        As[lk + 2][lrow] = a4.z; As[lk + 3][lrow] = a4.w;
        Bs[lk + 0][lrow] = b4.x; Bs[lk + 1][lrow] = b4.y;
        Bs[lk + 2][lrow] = b4.z; Bs[lk + 3][lrow] = b4.w;
        __syncthreads();
#pragma unroll
        for (int kk = 0; kk < 8; kk++) {
            float ar[8], br[8];
            *(float4*)&ar[0] = *(const float4*)&As[kk][ty * 4];
            *(float4*)&ar[4] = *(const float4*)&As[kk][64 + ty * 4];
            *(float4*)&br[0] = *(const float4*)&Bs[kk][tx * 4];
            *(float4*)&br[4] = *(const float4*)&Bs[kk][64 + tx * 4];
#pragma unroll
            for (int i = 0; i < 8; i++)
#pragma unroll
                for (int j = 0; j < 8; j++)
                    acc[i][j] += ar[i] * br[j];
        }
    }

#pragma unroll
    for (int mi = 0; mi < 2; mi++)
#pragma unroll
        for (int i = 0; i < 4; i++) {
            int row = m0 + mi * 64 + ty * 4 + i;
#pragma unroll
            for (int ni = 0; ni < 2; ni++) {
                int col = n0 + ni * 64 + tx * 4;
                float4 v = make_float4(acc[mi * 4 + i][ni * 4 + 0] * scale,
                                       acc[mi * 4 + i][ni * 4 + 1] * scale,
                                       acc[mi * 4 + i][ni * 4 + 2] * scale,
                                       acc[mi * 4 + i][ni * 4 + 3] * scale);
                *(float4*)(Sb + (size_t)row * Sq + col) = v;
            }
        }
}

// ===========================================================================
// Kernel 3: causal row softmax (in place).  Row q uses keys [0, q]; the tail
// (q, ceil128(q+1)) is zeroed so the PV GEMM needs no masking.
// grid = (S, B), 256 threads, row staged in 16KB smem.
// ===========================================================================
__global__ __launch_bounds__(256)
void softmax_rows()
{
    const int q = blockIdx.x, b = blockIdx.y;
    float* row = g_S + ((size_t)b * Sq + q) * Sq;
    const int len = q + 1;
    const int tid = threadIdx.x;

    __shared__ float buf[Sq];
    __shared__ float red[8];
    __shared__ float bval;

    // pass 1: load + max
    float m = -3.4e38f;
    for (int i = tid; i < len; i += 256) {
        float v = row[i];
        buf[i] = v;
        m = fmaxf(m, v);
    }
#pragma unroll
    for (int o = 16; o > 0; o >>= 1) m = fmaxf(m, __shfl_xor_sync(0xffffffffu, m, o));
    if ((tid & 31) == 0) red[tid >> 5] = m;
    __syncthreads();
    if (tid == 0) {
        float mm = red[0];
#pragma unroll
        for (int w = 1; w < 8; w++) mm = fmaxf(mm, red[w]);
        bval = mm;
    }
    __syncthreads();
    m = bval;

    // pass 2: exp + sum
    float s = 0.f;
    for (int i = tid; i < len; i += 256) {
        float e = expf(buf[i] - m);
        buf[i] = e;
        s += e;
    }
#pragma unroll
    for (int o = 16; o > 0; o >>= 1) s += __shfl_xor_sync(0xffffffffu, s, o);
    __syncthreads();
    if ((tid & 31) == 0) red[tid >> 5] = s;
    __syncthreads();
    if (tid == 0) {
        float ss = red[0];
#pragma unroll
        for (int w = 1; w < 8; w++) ss += red[w];
        bval = 1.f / ss;
    }
    __syncthreads();
    const float inv = bval;

    // pass 3: write normalized probs + zero tail up to tile boundary
    for (int i = tid; i < len; i += 256) row[i] = buf[i] * inv;
    const int padlen = ((q >> 7) + 1) << 7;
    for (int i = len + tid; i < padlen; i += 256) row[i] = 0.f;
}

// ===========================================================================
// Kernel 4: PV GEMM.  out[b,q,d] = sum_k P[b,q,k] * V[b,k,d]
// A = P (K-major), B = V (N-major: d contiguous). K-loop truncated at the
// causal boundary of the query tile. grid = (D/128, S/128, B).
// ===========================================================================
__global__ __launch_bounds__(256, 2)
void pv_gemm(float* __restrict__ out)
{
    const int b = blockIdx.z;
    const float* Pb = g_S + (size_t)b * Sq * Sq;
    const float* Vb = g_V + (size_t)b * Sq * Dd;
    float*       Ob = out + (size_t)b * Sq * Dd;

    const int m0 = blockIdx.y * 128;
    const int n0 = blockIdx.x * 128;
    const int tid = threadIdx.x;
    const int kend = m0 + 128;   // causal: keys < query-tile end

    __shared__ float As[8][128];
    __shared__ float Bs[8][128];

    const int lrow = tid >> 1;
    const int lk   = (tid & 1) * 4;
    const float* Aptr = Pb + (size_t)(m0 + lrow) * Sq + lk;

    const int bkk = tid >> 5;          // 0..7  (k row of B tile)
    const int bn4 = (tid & 31) * 4;    // 0..124 (n offset)
    const float* Bptr = Vb + (size_t)bkk * Dd + n0 + bn4;

    const int ty = tid >> 4, tx = tid & 15;

    float acc[8][8];
#pragma unroll
    for (int i = 0; i < 8; i++)
#pragma unroll
        for (int j = 0; j < 8; j++) acc[i][j] = 0.f;

    for (int k0 = 0; k0 < kend; k0 += 8) {
        float4 a4 = *(const float4*)(Aptr + k0);
        float4 b4 = *(const float4*)(Bptr + (size_t)k0 * Dd);
        __syncthreads();
        As[lk + 0][lrow] = a4.x; As[lk + 1][lrow] = a4.y;
        As[lk + 2][lrow] = a4.z; As[lk + 3][lrow] = a4.w;
        *(float4*)&Bs[bkk][bn4] = b4;
        __syncthreads();
#pragma unroll
        for (int kk = 0; kk < 8; kk++) {
            float ar[8], br[8];
            *(float4*)&ar[0] = *(const float4*)&As[kk][ty * 4];
            *(float4*)&ar[4] = *(const float4*)&As[kk][64 + ty * 4];
            *(float4*)&br[0] = *(const float4*)&Bs[kk][tx * 4];
            *(float4*)&br[4] = *(const float4*)&Bs[kk][64 + tx * 4];
#pragma unroll
            for (int i = 0; i < 8; i++)
#pragma unroll
                for (int j = 0; j < 8; j++)
                    acc[i][j] += ar[i] * br[j];
        }
    }

#pragma unroll
    for (int mi = 0; mi < 2; mi++)
#pragma unroll
        for (int i = 0; i < 4; i++) {
            int row = m0 + mi * 64 + ty * 4 + i;
#pragma unroll
            for (int ni = 0; ni < 2; ni++) {
                int col = n0 + ni * 64 + tx * 4;
                float4 v = make_float4(acc[mi * 4 + i][ni * 4 + 0],
                                       acc[mi * 4 + i][ni * 4 + 1],
                                       acc[mi * 4 + i][ni * 4 + 2],
                                       acc[mi * 4 + i][ni * 4 + 3]);
                *(float4*)(Ob + (size_t)row * Dd + col) = v;
            }
        }
}

// ===========================================================================
extern "C" void kernel_launch(void* const* d_in, const int* in_sizes, int n_in,
                              void* d_out, int out_size)
{
    const float* X  = (const float*)d_in[0];   // [4,4096,1024]
    const float* Wq = (const float*)d_in[1];   // [1024,1024]
    const float* Wk = (const float*)d_in[2];
    const float* Wv = (const float*)d_in[3];
    float* out = (float*)d_out;                // [4,4096,1024]

    dim3 g1(Dd / 128, MS / 128, 3);
    qkv_gemm<<<g1, 256>>>(X, Wq, Wk, Wv);

    dim3 g2(Sq / 128, Sq / 128, Bz);
    scores_gemm<<<g2, 256>>>();

    dim3 g3(Sq, Bz);
    softmax_rows<<<g3, 256>>>();

    dim3 g4(Dd / 128, Sq / 128, Bz);
    pv_gemm<<<g4, 256>>>(out);
}

// round 3
// speedup vs baseline: 3.0223x; 3.0223x over previous
#include <cuda_runtime.h>
#include <cuda_bf16.h>
#include <cstdint>

#define Bz 4
#define Sq 4096
#define Dd 1024
#define MS (Bz * Sq)

typedef __nv_bfloat16 bf16;

// ---------------- scratch (device globals; no allocations allowed) --------
__device__ bf16 g_Xh[(size_t)MS * Dd], g_Xl[(size_t)MS * Dd];
__device__ bf16 g_Wh[3][Dd * Dd],      g_Wl[3][Dd * Dd];
__device__ bf16 g_Qh[(size_t)MS * Dd], g_Ql[(size_t)MS * Dd];
__device__ bf16 g_Kh[(size_t)MS * Dd], g_Kl[(size_t)MS * Dd];
__device__ bf16 g_Vh[(size_t)MS * Dd], g_Vl[(size_t)MS * Dd];
__device__ bf16 g_Vth[(size_t)MS * Dd], g_Vtl[(size_t)MS * Dd];  // [b][d][s]
__device__ float g_S[(size_t)Bz * Sq * Sq];                       // raw scores
__device__ bf16 g_Ph[(size_t)Bz * Sq * Sq], g_Pl[(size_t)Bz * Sq * Sq];

// =========================== PTX helpers ==================================
__device__ __forceinline__ uint32_t smem_u32(const void* p) {
    uint32_t a;
    asm("{ .reg .u64 t; cvta.to.shared.u64 t, %1; cvt.u32.u64 %0, t; }"
        : "=r"(a) : "l"(p));
    return a;
}
__device__ __forceinline__ void cp16(uint32_t s, const void* g) {
    asm volatile("cp.async.cg.shared.global [%0], [%1], 16;" :: "r"(s), "l"(g));
}
__device__ __forceinline__ void cp_commit() {
    asm volatile("cp.async.commit_group;" ::: "memory");
}
__device__ __forceinline__ void cp_wait1() {
    asm volatile("cp.async.wait_group 1;" ::: "memory");
}
__device__ __forceinline__ void ldm_x4(uint32_t a, uint32_t& r0, uint32_t& r1,
                                       uint32_t& r2, uint32_t& r3) {
    asm volatile("ldmatrix.sync.aligned.m8n8.x4.shared.b16 {%0,%1,%2,%3}, [%4];"
                 : "=r"(r0), "=r"(r1), "=r"(r2), "=r"(r3) : "r"(a));
}
__device__ __forceinline__ void mma_bf16(float (&c)[4],
                                         uint32_t a0, uint32_t a1, uint32_t a2, uint32_t a3,
                                         uint32_t b0, uint32_t b1) {
    asm volatile("mma.sync.aligned.m16n8k16.row.col.f32.bf16.bf16.f32 "
                 "{%0,%1,%2,%3}, {%4,%5,%6,%7}, {%8,%9}, {%0,%1,%2,%3};"
                 : "+f"(c[0]), "+f"(c[1]), "+f"(c[2]), "+f"(c[3])
                 : "r"(a0), "r"(a1), "r"(a2), "r"(a3), "r"(b0), "r"(b1));
}

// =========================== GEMM core ====================================
// C[128,128] = A[128,kLen] * B[128,kLen]^T, both K-major bf16 hi/lo planes.
// 256 threads, warp grid 2(M) x 4(N), warp tile 64x32, KC=64, 3-stage cp.async.
#define KC 64
#define STAGES 3
#define STAGE_BYTES 65536       // 4 planes x 128x64 bf16 (16KB each)
#define PL_AL 16384
#define PL_BH 32768
#define PL_BL 49152
#define SMEM_BYTES (STAGES * STAGE_BYTES)   // 196608

__device__ __forceinline__ void stage_copy(uint32_t sb, int tid,
    const bf16* __restrict__ Ah, const bf16* __restrict__ Al, int lda,
    const bf16* __restrict__ Bh, const bf16* __restrict__ Bl, int ldb, int k0)
{
#pragma unroll
    for (int i = 0; i < 4; i++) {
        int q = tid + (i << 8);
        int m = q >> 3, c = q & 7;
        uint32_t so = (uint32_t)(m * 128 + ((c ^ (m & 7)) << 4));
        size_t ga = (size_t)m * lda + k0 + c * 8;
        size_t gb = (size_t)m * ldb + k0 + c * 8;
        cp16(sb + so,         Ah + ga);
        cp16(sb + PL_AL + so, Al + ga);
        cp16(sb + PL_BH + so, Bh + gb);
        cp16(sb + PL_BL + so, Bl + gb);
    }
}

// MODE: 0 = split bf16 out (hi/lo planes), 1 = fp32 out with scale, 2 = fp32 out
template <int MODE>
__device__ __forceinline__ void gemm_core(
    const bf16* __restrict__ Ah, const bf16* __restrict__ Al, int lda,
    const bf16* __restrict__ Bh, const bf16* __restrict__ Bl, int ldb,
    int kLen,
    float* __restrict__ Cf, bf16* __restrict__ Ch, bf16* __restrict__ Cl,
    int ldc, float scale)
{
    extern __shared__ char dyn[];
    const uint32_t sbase = smem_u32(dyn);
    const int tid = threadIdx.x;
    const int l = tid & 31, wid = tid >> 5;
    const int wm = wid & 1, wn = wid >> 1;
    const int kT = kLen >> 6;

    float acc[4][4][4];
#pragma unroll
    for (int i = 0; i < 4; i++)
#pragma unroll
        for (int j = 0; j < 4; j++)
#pragma unroll
            for (int k = 0; k < 4; k++) acc[i][j][k] = 0.f;

    // prologue: stages 0,1
    stage_copy(sbase, tid, Ah, Al, lda, Bh, Bl, ldb, 0);
    cp_commit();
    if (kT > 1) stage_copy(sbase + STAGE_BYTES, tid, Ah, Al, lda, Bh, Bl, ldb, KC);
    cp_commit();

    const int arow = (l & 15);
    const int c0A = (l >> 4) & 1;
    const int brow = (l & 7) + ((l & 16) >> 1);   // +8 for upper half-warp
    const int c0B = (l >> 3) & 1;
    const int lm7 = l & 7;

    for (int kt = 0; kt < kT; kt++) {
        cp_wait1();
        __syncthreads();
        if (kt + 2 < kT) {
            int slot = kt + 2; while (slot >= STAGES) slot -= STAGES;
            stage_copy(sbase + slot * STAGE_BYTES, tid, Ah, Al, lda, Bh, Bl, ldb,
                       (kt + 2) * KC);
        }
        cp_commit();

        int cs = kt; while (cs >= STAGES) cs -= STAGES;
        const uint32_t sb = sbase + cs * STAGE_BYTES;

#pragma unroll
        for (int k16 = 0; k16 < 4; k16++) {
            uint32_t ah[4][4], alr[4][4], bh[4][2], blr[4][2];
#pragma unroll
            for (int tm = 0; tm < 4; tm++) {
                uint32_t off = (uint32_t)((wm * 64 + tm * 16 + arow) * 128)
                             + (uint32_t)(((2 * k16 + c0A) ^ lm7) << 4);
                ldm_x4(sb + off,         ah[tm][0],  ah[tm][1],  ah[tm][2],  ah[tm][3]);
                ldm_x4(sb + PL_AL + off, alr[tm][0], alr[tm][1], alr[tm][2], alr[tm][3]);
            }
#pragma unroll
            for (int pr = 0; pr < 2; pr++) {
                uint32_t off = (uint32_t)((wn * 32 + pr * 16 + brow) * 128)
                             + (uint32_t)(((2 * k16 + c0B) ^ lm7) << 4);
                uint32_t r0, r1, r2, r3;
                ldm_x4(sb + PL_BH + off, r0, r1, r2, r3);
                bh[pr * 2][0] = r0; bh[pr * 2][1] = r1;
                bh[pr * 2 + 1][0] = r2; bh[pr * 2 + 1][1] = r3;
                ldm_x4(sb + PL_BL + off, r0, r1, r2, r3);
                blr[pr * 2][0] = r0; blr[pr * 2][1] = r1;
                blr[pr * 2 + 1][0] = r2; blr[pr * 2 + 1][1] = r3;
            }
#pragma unroll
            for (int tm = 0; tm < 4; tm++)
#pragma unroll
                for (int tn = 0; tn < 4; tn++) {
                    mma_bf16(acc[tm][tn], ah[tm][0], ah[tm][1], ah[tm][2], ah[tm][3],
                             bh[tn][0], bh[tn][1]);
                    mma_bf16(acc[tm][tn], ah[tm][0], ah[tm][1], ah[tm][2], ah[tm][3],
                             blr[tn][0], blr[tn][1]);
                    mma_bf16(acc[tm][tn], alr[tm][0], alr[tm][1], alr[tm][2], alr[tm][3],
                             bh[tn][0], bh[tn][1]);
                }
        }
    }

    // epilogue
    const int g = l >> 2, tg = l & 3;
#pragma unroll
    for (int tm = 0; tm < 4; tm++) {
        const int r0 = wm * 64 + tm * 16 + g;
#pragma unroll
        for (int tn = 0; tn < 4; tn++) {
            const int col = wn * 32 + tn * 8 + tg * 2;
            const float* a = acc[tm][tn];
            if (MODE != 0) {
                float2 v0 = make_float2(a[0] * scale, a[1] * scale);
                float2 v1 = make_float2(a[2] * scale, a[3] * scale);
                *(float2*)(Cf + (size_t)r0 * ldc + col) = v0;
                *(float2*)(Cf + (size_t)(r0 + 8) * ldc + col) = v1;
            } else {
#pragma unroll
                for (int h = 0; h < 2; h++) {
                    float x0 = a[2 * h], x1 = a[2 * h + 1];
                    bf16 h0 = __float2bfloat16_rn(x0);
                    bf16 h1 = __float2bfloat16_rn(x1);
                    bf16 l0 = __float2bfloat16_rn(x0 - __bfloat162float(h0));
                    bf16 l1 = __float2bfloat16_rn(x1 - __bfloat162float(h1));
                    size_t o = (size_t)(r0 + 8 * h) * ldc + col;
                    *(__nv_bfloat162*)(Ch + o) = __nv_bfloat162(h0, h1);
                    *(__nv_bfloat162*)(Cl + o) = __nv_bfloat162(l0, l1);
                }
            }
        }
    }
}

// =========================== GEMM kernels =================================
__global__ __launch_bounds__(256, 1)
void k_qkv()
{
    const int z = blockIdx.z;
    bf16* Oh = (z == 0) ? g_Qh : (z == 1) ? g_Kh : g_Vh;
    bf16* Ol = (z == 0) ? g_Ql : (z == 1) ? g_Kl : g_Vl;
    const size_t m0 = (size_t)blockIdx.y * 128;
    const size_t n0 = (size_t)blockIdx.x * 128;
    gemm_core<0>(g_Xh + m0 * Dd, g_Xl + m0 * Dd, Dd,
                 g_Wh[z] + n0 * Dd, g_Wl[z] + n0 * Dd, Dd, Dd,
                 nullptr, Oh + m0 * Dd + n0, Ol + m0 * Dd + n0, Dd, 1.0f);
}

__global__ __launch_bounds__(256, 1)
void k_scores()
{
    const int kt = blockIdx.x, qt = blockIdx.y, b = blockIdx.z;
    if (kt > qt) return;
    const size_t qo = (size_t)b * Sq * Dd + (size_t)qt * 128 * Dd;
    const size_t ko = (size_t)b * Sq * Dd + (size_t)kt * 128 * Dd;
    gemm_core<1>(g_Qh + qo, g_Ql + qo, Dd,
                 g_Kh + ko, g_Kl + ko, Dd, Dd,
                 g_S + (size_t)b * Sq * Sq + (size_t)qt * 128 * Sq + kt * 128,
                 nullptr, nullptr, Sq, 0.03125f);
}

__global__ __launch_bounds__(256, 1)
void k_pv(float* __restrict__ out)
{
    const int b = blockIdx.z;
    const size_t m0 = (size_t)blockIdx.y * 128;
    const size_t n0 = (size_t)blockIdx.x * 128;
    const size_t po = (size_t)b * Sq * Sq + m0 * Sq;
    const size_t vo = (size_t)b * Sq * Dd + n0 * Sq;
    gemm_core<2>(g_Ph + po, g_Pl + po, Sq,
                 g_Vth + vo, g_Vtl + vo, Sq, (int)(m0 + 128),
                 out + (size_t)b * Sq * Dd + m0 * Dd + n0,
                 nullptr, nullptr, Dd, 1.0f);
}

// =========================== aux kernels ==================================
__global__ __launch_bounds__(256)
void k_split(const float* __restrict__ s, bf16* __restrict__ h,
             bf16* __restrict__ l, int n4)
{
    int i = blockIdx.x * 256 + threadIdx.x;
    if (i >= n4) return;
    float4 v = ((const float4*)s)[i];
    bf16 h0 = __float2bfloat16_rn(v.x), h1 = __float2bfloat16_rn(v.y);
    bf16 h2 = __float2bfloat16_rn(v.z), h3 = __float2bfloat16_rn(v.w);
    bf16 l0 = __float2bfloat16_rn(v.x - __bfloat162float(h0));
    bf16 l1 = __float2bfloat16_rn(v.y - __bfloat162float(h1));
    bf16 l2 = __float2bfloat16_rn(v.z - __bfloat162float(h2));
    bf16 l3 = __float2bfloat16_rn(v.w - __bfloat162float(h3));
    ((__nv_bfloat162*)h)[2 * i]     = __nv_bfloat162(h0, h1);
    ((__nv_bfloat162*)h)[2 * i + 1] = __nv_bfloat162(h2, h3);
    ((__nv_bfloat162*)l)[2 * i]     = __nv_bfloat162(l0, l1);
    ((__nv_bfloat162*)l)[2 * i + 1] = __nv_bfloat162(l2, l3);
}

__global__ void k_vtrans()
{
    __shared__ bf16 t[32][33];
    const int zz = blockIdx.z, b = zz >> 1, pl = zz & 1;
    const bf16* V = (pl ? g_Vl : g_Vh) + (size_t)b * Sq * Dd;
    bf16*       T = (pl ? g_Vtl : g_Vth) + (size_t)b * Sq * Dd;
    const int s0 = blockIdx.x * 32, d0 = blockIdx.y * 32;
    const int x = threadIdx.x, y = threadIdx.y;
#pragma unroll
    for (int i = 0; i < 32; i += 8)
        t[y + i][x] = V[(size_t)(s0 + y + i) * Dd + d0 + x];
    __syncthreads();
#pragma unroll
    for (int i = 0; i < 32; i += 8)
        T[(size_t)(d0 + y + i) * Sq + s0 + x] = t[x][y + i];
}

__global__ __launch_bounds__(256)
void k_softmax()
{
    const int q = blockIdx.x, b = blockIdx.y;
    const size_t ro = ((size_t)b * Sq + q) * Sq;
    const float* row = g_S + ro;
    const int len = q + 1;
    const int tid = threadIdx.x;

    __shared__ float buf[Sq];
    __shared__ float red[8];
    __shared__ float bval;

    float m = -3.4e38f;
    for (int i = tid; i < len; i += 256) {
        float v = row[i];
        buf[i] = v;
        m = fmaxf(m, v);
    }
#pragma unroll
    for (int o = 16; o > 0; o >>= 1) m = fmaxf(m, __shfl_xor_sync(0xffffffffu, m, o));
    if ((tid & 31) == 0) red[tid >> 5] = m;
    __syncthreads();
    if (tid == 0) {
        float mm = red[0];
#pragma unroll
        for (int w = 1; w < 8; w++) mm = fmaxf(mm, red[w]);
        bval = mm;
    }
    __syncthreads();
    m = bval;

    float s = 0.f;
    for (int i = tid; i < len; i += 256) {
        float e = __expf(buf[i] - m);
        buf[i] = e;
        s += e;
    }
#pragma unroll
    for (int o = 16; o > 0; o >>= 1) s += __shfl_xor_sync(0xffffffffu, s, o);
    __syncthreads();
    if ((tid & 31) == 0) red[tid >> 5] = s;
    __syncthreads();
    if (tid == 0) {
        float ss = red[0];
#pragma unroll
        for (int w = 1; w < 8; w++) ss += red[w];
        bval = 1.f / ss;
    }
    __syncthreads();
    const float inv = bval;

    for (int i = tid; i < len; i += 256) {
        float p = buf[i] * inv;
        bf16 h = __float2bfloat16_rn(p);
        bf16 l = __float2bfloat16_rn(p - __bfloat162float(h));
        g_Ph[ro + i] = h;
        g_Pl[ro + i] = l;
    }
    const int padlen = ((q >> 7) + 1) << 7;
    for (int i = len + tid; i < padlen; i += 256) {
        g_Ph[ro + i] = __float2bfloat16_rn(0.f);
        g_Pl[ro + i] = __float2bfloat16_rn(0.f);
    }
}

// ===========================================================================
extern "C" void kernel_launch(void* const* d_in, const int* in_sizes, int n_in,
                              void* d_out, int out_size)
{
    const float* X  = (const float*)d_in[0];
    const float* Wq = (const float*)d_in[1];
    const float* Wk = (const float*)d_in[2];
    const float* Wv = (const float*)d_in[3];
    float* out = (float*)d_out;

    static int s_init = 0;
    if (!s_init) {
        cudaFuncSetAttribute(k_qkv,    cudaFuncAttributeMaxDynamicSharedMemorySize, SMEM_BYTES);
        cudaFuncSetAttribute(k_scores, cudaFuncAttributeMaxDynamicSharedMemorySize, SMEM_BYTES);
        cudaFuncSetAttribute(k_pv,     cudaFuncAttributeMaxDynamicSharedMemorySize, SMEM_BYTES);
        s_init = 1;
    }

    bf16 *xh, *xl, *wh, *wl;
    cudaGetSymbolAddress((void**)&xh, g_Xh);
    cudaGetSymbolAddress((void**)&xl, g_Xl);
    cudaGetSymbolAddress((void**)&wh, g_Wh);
    cudaGetSymbolAddress((void**)&wl, g_Wl);

    k_split<<<(MS * Dd / 4 + 255) / 256, 256>>>(X, xh, xl, MS * Dd / 4);
    k_split<<<(Dd * Dd / 4 + 255) / 256, 256>>>(Wq, wh,              wl,              Dd * Dd / 4);
    k_split<<<(Dd * Dd / 4 + 255) / 256, 256>>>(Wk, wh + Dd * Dd,    wl + Dd * Dd,    Dd * Dd / 4);
    k_split<<<(Dd * Dd / 4 + 255) / 256, 256>>>(Wv, wh + 2 * Dd * Dd, wl + 2 * Dd * Dd, Dd * Dd / 4);

    k_qkv<<<dim3(Dd / 128, MS / 128, 3), 256, SMEM_BYTES>>>();
    k_vtrans<<<dim3(Sq / 32, Dd / 32, Bz * 2), dim3(32, 8)>>>();
    k_scores<<<dim3(Sq / 128, Sq / 128, Bz), 256, SMEM_BYTES>>>();
    k_softmax<<<dim3(Sq, Bz), 256>>>();
    k_pv<<<dim3(Dd / 128, Sq / 128, Bz), 256, SMEM_BYTES>>>(out);
}